// round 2
// baseline (speedup 1.0000x reference)
#include <cuda_runtime.h>
#include <cuda_bf16.h>

// LRN spatial 5x5: out = x / (2 + 1e-4 * boxsum5x5(x^2))^0.75
// x: (16, 96, 224, 224) fp32, zero padding.
//
// R2 design: register-streaming separable stencil, NO shared memory.
//   - Thread owns one column, streams 112 rows (2 strips per plane).
//   - Vertical 5-tap: sliding window of x values in registers,
//     vsum updated incrementally (+e^2 ... -a^2).
//   - Horizontal 5-tap via warp shuffles (3 shuffles per output):
//       p[l] = v[l] + v[l+1];  h[l] = p[l-2] + v[l] + p[l+1]
//   - Warps overlap 4 halo lanes: 32 lanes load, lanes 2..29 write
//     28 consecutive columns. 8 warps x 28 = 224 = full plane width.
//   - d^-0.75 = rsqrt(d) * sqrt(rsqrt(d)).

#define LRN_W 224
#define LRN_H 224
#define LRN_STRIP 112   // rows per block (2 strips per plane)

__global__ __launch_bounds__(256, 8)
void lrn_kernel(const float* __restrict__ x, float* __restrict__ out) {
    const int plane = blockIdx.x;                  // n*96 + c, 0..1535
    const int r0    = blockIdx.y * LRN_STRIP;      // 0 or 112
    const int warp  = threadIdx.x >> 5;            // 0..7
    const int lane  = threadIdx.x & 31;
    const int col   = warp * 28 + lane - 2;        // -2 .. 225
    const bool colok  = (col >= 0) && (col < LRN_W);
    const bool writer = (lane >= 2) && (lane < 30);  // cols warp*28 .. warp*28+27

    const float* __restrict__ px   = x   + (size_t)plane * (LRN_H * LRN_W);
    float*       __restrict__ pout = out + (size_t)plane * (LRN_H * LRN_W);

    // Preload rows r0-2 .. r0+1 (zeros outside the plane / outside columns).
    float a, b, c, d;
    {
        int r;
        r = r0 - 2; a = (colok && r >= 0)    ? __ldg(px + (size_t)r * LRN_W + col) : 0.f;
        r = r0 - 1; b = (colok && r >= 0)    ? __ldg(px + (size_t)r * LRN_W + col) : 0.f;
        r = r0;     c = (colok)              ? __ldg(px + (size_t)r * LRN_W + col) : 0.f;
        r = r0 + 1; d = (colok && r < LRN_H) ? __ldg(px + (size_t)r * LRN_W + col) : 0.f;
    }
    float vs = a * a + b * b + c * c + d * d;   // sum of squares rows r0-2..r0+1

    #pragma unroll 4
    for (int i = 0; i < LRN_STRIP; ++i) {
        const int r = r0 + i;
        // load row r+2 (bottom of window)
        float e = (colok && (r + 2) < LRN_H)
                  ? __ldg(px + (size_t)(r + 2) * LRN_W + col) : 0.f;
        vs += e * e;                             // vs = vertical 5-tap ssq at row r

        // horizontal 5-tap via shuffles
        float p = vs + __shfl_down_sync(0xffffffffu, vs, 1);          // v[l]+v[l+1]
        float h = __shfl_up_sync(0xffffffffu, p, 2) + vs
                + __shfl_down_sync(0xffffffffu, p, 1);                // 5-tap

        float den = fmaf(1e-4f, h, 2.0f);
        float rr  = rsqrtf(den);                 // den^-0.5
        float val = c * (rr * sqrtf(rr));        // x * den^-0.75

        if (writer)
            pout[(size_t)r * LRN_W + col] = val;

        vs -= a * a;                             // drop top row of window
        a = b; b = c; c = d; d = e;              // slide (renamed away by unroll)
    }
}

extern "C" void kernel_launch(void* const* d_in, const int* in_sizes, int n_in,
                              void* d_out, int out_size) {
    const float* x = (const float*)d_in[0];
    float* out = (float*)d_out;
    (void)in_sizes; (void)n_in; (void)out_size;
    dim3 grid(16 * 96, LRN_H / LRN_STRIP);   // 1536 planes x 2 row-strips
    lrn_kernel<<<grid, 256>>>(x, out);
}

// round 3
// speedup vs baseline: 1.7046x; 1.7046x over previous
#include <cuda_runtime.h>
#include <cuda_bf16.h>

// LRN spatial 5x5: out = x / (2 + 1e-4 * boxsum5x5(x^2))^0.75
// x: (16, 96, 224, 224) fp32, zero padding.
//
// R3: hybrid of R1 (parallel coalesced tile load -> shared, hides DRAM
// latency with high MLP) and R2 (register vertical sliding sum + shuffle
// horizontal, minimal shared traffic).
//   Block = 28 output rows x 224 cols of one (n,c) plane (+2-row halo).
//   Phase A: 256 threads load 32x224 tile as float4 into padded shared.
//   Stream:  8 warps; warp owns 28 cols (lanes overlap 4 halo lanes),
//            streams 28 rows. x read from shared (29cyc, hidden).
//            vertical ssq: register sliding window (+e^2 / -a^2).
//            horizontal 5-tap: p[l]=v[l]+v[l+1]; h=p[l-2]+v[l]+p[l+1]
//            (3 shuffles). d^-0.75 = rsqrt(d)*sqrt(rsqrt(d)).

#define LRN_W   224
#define LRN_H   224
#define LRN_TH  28              // output rows per block
#define LRN_INR (LRN_TH + 4)    // 32 tile rows incl. halo
#define LRN_XSW 232             // 4 pad + 224 + 4 pad
#define LRN_NG  (LRN_INR * (LRN_W / 4))   // 32*56 = 1792 float4 groups

__global__ __launch_bounds__(256, 4)
void lrn_kernel(const float* __restrict__ x, float* __restrict__ out) {
    __shared__ float xs[LRN_INR][LRN_XSW];   // global col c -> idx c+4

    const int plane = blockIdx.x;                  // n*96 + c
    const int r0    = blockIdx.y * LRN_TH;         // 0,28,...,196
    const int tid   = threadIdx.x;
    const float* __restrict__ px   = x   + (size_t)plane * (LRN_H * LRN_W);
    float*       __restrict__ pout = out + (size_t)plane * (LRN_H * LRN_W);

    // ---- Phase A: coalesced float4 tile load (rows r0-2 .. r0+29) ----
    #pragma unroll
    for (int k = 0; k < LRN_NG / 256; ++k) {       // 7 groups per thread
        int g    = k * 256 + tid;
        int row  = g / (LRN_W / 4);
        int c4   = (g % (LRN_W / 4)) * 4;
        int grow = r0 - 2 + row;
        float4 v = make_float4(0.f, 0.f, 0.f, 0.f);
        if (grow >= 0 && grow < LRN_H)
            v = *reinterpret_cast<const float4*>(px + (size_t)grow * LRN_W + c4);
        *reinterpret_cast<float4*>(&xs[row][4 + c4]) = v;
    }
    // zero column pads (idx 2,3,228,229 for every tile row)
    if (tid < LRN_INR * 4) {
        int row = tid >> 2;
        int j   = tid & 3;
        int idx = (j < 2) ? (2 + j) : (226 + j);   // 2,3,228,229
        xs[row][idx] = 0.f;
    }
    __syncthreads();

    // ---- Stream phase: 8 warps x 28 columns, 28 rows each ----
    const int warp = tid >> 5;
    const int lane = tid & 31;
    const int cidx = warp * 28 + lane + 2;         // xs column index (col+4), 2..229
    const bool writer = (lane >= 2) && (lane < 30);
    const int col  = warp * 28 + lane - 2;         // global column of this lane

    float a = xs[0][cidx];
    float b = xs[1][cidx];
    float c = xs[2][cidx];
    float d = xs[3][cidx];
    float vs = a * a + b * b + c * c + d * d;

    #pragma unroll 4
    for (int i = 0; i < LRN_TH; ++i) {
        float e = xs[i + 4][cidx];
        vs += e * e;                                // vertical 5-tap ssq @ row r0+i

        float p = vs + __shfl_down_sync(0xffffffffu, vs, 1);
        float h = __shfl_up_sync(0xffffffffu, p, 2) + vs
                + __shfl_down_sync(0xffffffffu, p, 1);

        float den = fmaf(1e-4f, h, 2.0f);
        float rr  = rsqrtf(den);                    // den^-0.5
        float val = c * (rr * sqrtf(rr));           // x * den^-0.75

        if (writer)
            pout[(size_t)(r0 + i) * LRN_W + col] = val;

        vs -= a * a;
        a = b; b = c; c = d; d = e;
    }
}

extern "C" void kernel_launch(void* const* d_in, const int* in_sizes, int n_in,
                              void* d_out, int out_size) {
    const float* x = (const float*)d_in[0];
    float* out = (float*)d_out;
    (void)in_sizes; (void)n_in; (void)out_size;
    dim3 grid(16 * 96, LRN_H / LRN_TH);    // 1536 planes x 8 row-strips
    lrn_kernel<<<grid, 256>>>(x, out);
}

// round 4
// speedup vs baseline: 1.9681x; 1.1546x over previous
#include <cuda_runtime.h>
#include <cuda_bf16.h>

// LRN spatial 5x5: out = x / (2 + 1e-4 * boxsum5x5(x^2))^0.75
// x: (16, 96, 224, 224) fp32, zero padding.
//
// R4 = R3 architecture (coalesced float4 tile -> shared; register vertical
// sliding ssq; 3-shuffle horizontal 5-tap) with the issue-pipe fat removed:
//   - __powf(den, -0.75f)  -> MUFU.LG2 + FMUL + MUFU.EX2 (no IEEE sqrt seq)
//   - pointer-walk addressing in the stream loop
//   - __launch_bounds__(256, 6): regs <= 42 -> 6 blocks/SM (75% occ)

#define LRN_W   224
#define LRN_H   224
#define LRN_TH  28              // output rows per block
#define LRN_INR (LRN_TH + 4)    // 32 tile rows incl. halo
#define LRN_XSW 232             // 4 pad + 224 + 4 pad
#define LRN_NG  (LRN_INR * (LRN_W / 4))   // 32*56 = 1792 float4 groups

__global__ __launch_bounds__(256, 6)
void lrn_kernel(const float* __restrict__ x, float* __restrict__ out) {
    __shared__ float xs[LRN_INR][LRN_XSW];   // global col c -> idx c+4

    const int plane = blockIdx.x;                  // n*96 + c
    const int r0    = blockIdx.y * LRN_TH;         // 0,28,...,196
    const int tid   = threadIdx.x;
    const float* __restrict__ px   = x   + (size_t)plane * (LRN_H * LRN_W);
    float*       __restrict__ pout = out + (size_t)plane * (LRN_H * LRN_W);

    // ---- Phase A: coalesced float4 tile load (rows r0-2 .. r0+29) ----
    #pragma unroll
    for (int k = 0; k < LRN_NG / 256; ++k) {       // 7 groups per thread
        int g    = k * 256 + tid;
        int row  = g / (LRN_W / 4);
        int c4   = (g % (LRN_W / 4)) * 4;
        int grow = r0 - 2 + row;
        float4 v = make_float4(0.f, 0.f, 0.f, 0.f);
        if (grow >= 0 && grow < LRN_H)
            v = *reinterpret_cast<const float4*>(px + (size_t)grow * LRN_W + c4);
        *reinterpret_cast<float4*>(&xs[row][4 + c4]) = v;
    }
    // zero column pads (idx 2,3,228,229 for every tile row)
    if (tid < LRN_INR * 4) {
        int row = tid >> 2;
        int j   = tid & 3;
        int idx = (j < 2) ? (2 + j) : (226 + j);   // 2,3,228,229
        xs[row][idx] = 0.f;
    }
    __syncthreads();

    // ---- Stream phase: 8 warps x 28 columns, 28 rows each ----
    const int warp = tid >> 5;
    const int lane = tid & 31;
    const int cidx = warp * 28 + lane + 2;         // xs column index (col+4)
    const bool writer = (lane >= 2) && (lane < 30);
    const int col  = warp * 28 + lane - 2;         // global column of this lane

    const float* xp = &xs[4][0] + cidx;            // walks down tile rows
    float* po = pout + (size_t)r0 * LRN_W + col;   // walks down output rows

    float a = xs[0][cidx];
    float b = xs[1][cidx];
    float c = xs[2][cidx];
    float d = xs[3][cidx];
    float vs = a * a + b * b + c * c + d * d;

    #pragma unroll 2
    for (int i = 0; i < LRN_TH; ++i) {
        float e = *xp;                              // row r0+i+2 (bottom of window)
        xp += LRN_XSW;
        vs = fmaf(e, e, vs);                        // vertical 5-tap ssq @ row r0+i

        float p = vs + __shfl_down_sync(0xffffffffu, vs, 1);
        float h = __shfl_up_sync(0xffffffffu, p, 2) + vs
                + __shfl_down_sync(0xffffffffu, p, 1);

        float den = fmaf(1e-4f, h, 2.0f);
        float dn  = __powf(den, -0.75f);            // LG2 + FMUL + EX2
        float val = c * dn;

        if (writer) *po = val;
        po += LRN_W;

        vs = fmaf(-a, a, vs);
        a = b; b = c; c = d; d = e;
    }
}

extern "C" void kernel_launch(void* const* d_in, const int* in_sizes, int n_in,
                              void* d_out, int out_size) {
    const float* x = (const float*)d_in[0];
    float* out = (float*)d_out;
    (void)in_sizes; (void)n_in; (void)out_size;
    dim3 grid(16 * 96, LRN_H / LRN_TH);    // 1536 planes x 8 row-strips
    lrn_kernel<<<grid, 256>>>(x, out);
}

// round 5
// speedup vs baseline: 2.1336x; 1.0841x over previous
#include <cuda_runtime.h>
#include <cuda_bf16.h>

// LRN spatial 5x5: out = x / (2 + 1e-4 * boxsum5x5(x^2))^0.75
// x: (16, 96, 224, 224) fp32, zero padding.
//
// R5: float4-per-thread separable stencil. No shuffles, no halo lanes.
//   Block = 32 output rows x 224 cols of one plane (+2-row halo tile in smem).
//   224 threads = 56 col-groups (4 cols each) x 4 row-groups (8 rows each).
//   Per row: 3 aligned LDS.128 -> horizontal 5-tap ssq for 4 cols (register
//   sliding sum). Vertical 5-tap via register ring hist[4] (add new h,
//   output, subtract h from 4 rows back). d^-0.75 via __powf (LG2+FMUL+EX2).
//   Output: STG.128, fully useful lanes.

#define LRN_W   224
#define LRN_H   224
#define LRN_R   8                    // rows per row-group
#define LRN_RG  4                    // row-groups per block
#define LRN_TH  (LRN_R * LRN_RG)     // 32 output rows per block
#define LRN_TR  (LRN_TH + 4)         // 36 tile rows
#define LRN_XSW 232                  // 4 pad + 224 + 4 pad
#define LRN_CG  56                   // col-groups per row

// Horizontal 5-tap sum-of-squares for 4 columns starting at col 4g.
// rowp = &xs[row][0]; col c maps to index c+4. Loads idx 4g, 4g+4, 4g+8
// (cols 4g-4 .. 4g+7). Also returns b = raw x at cols 4g..4g+3.
__device__ __forceinline__ float4 hsum_row(const float* __restrict__ rowp,
                                           int g4, float4* __restrict__ bx) {
    float4 a = *reinterpret_cast<const float4*>(rowp + g4);
    float4 b = *reinterpret_cast<const float4*>(rowp + g4 + 4);
    float4 c = *reinterpret_cast<const float4*>(rowp + g4 + 8);
    *bx = b;
    float q0 = a.z * a.z, q1 = a.w * a.w;   // cols 4g-2, 4g-1
    float q2 = b.x * b.x, q3 = b.y * b.y;
    float q4 = b.z * b.z, q5 = b.w * b.w;
    float q6 = c.x * c.x, q7 = c.y * c.y;   // cols 4g+4, 4g+5
    float4 h;
    h.x = q0 + q1 + q2 + q3 + q4;
    h.y = h.x - q0 + q5;
    h.z = h.y - q1 + q6;
    h.w = h.z - q2 + q7;
    return h;
}

__global__ __launch_bounds__(224, 4)
void lrn_kernel(const float* __restrict__ x, float* __restrict__ out) {
    __shared__ float xs[LRN_TR][LRN_XSW];   // global col c -> idx c+4

    const int plane = blockIdx.x;                 // n*96 + c
    const int r0    = blockIdx.y * LRN_TH;        // 0,32,...,192
    const int tid   = threadIdx.x;
    const float* __restrict__ px   = x   + (size_t)plane * (LRN_H * LRN_W);
    float*       __restrict__ pout = out + (size_t)plane * (LRN_H * LRN_W);

    // ---- Phase A: coalesced float4 tile load (rows r0-2 .. r0+33) ----
    #pragma unroll
    for (int k = 0; k < (LRN_TR * LRN_CG) / 224; ++k) {   // 9 per thread
        int gg   = k * 224 + tid;
        int row  = gg / LRN_CG;
        int c4   = (gg % LRN_CG) * 4;
        int grow = r0 - 2 + row;
        float4 v = make_float4(0.f, 0.f, 0.f, 0.f);
        if (grow >= 0 && grow < LRN_H)
            v = *reinterpret_cast<const float4*>(px + (size_t)grow * LRN_W + c4);
        *reinterpret_cast<float4*>(&xs[row][4 + c4]) = v;
    }
    // zero column pads (idx 2,3 = cols -2,-1; idx 228,229 = cols 224,225)
    if (tid < LRN_TR * 4) {
        int row = tid >> 2;
        int j   = tid & 3;
        int idx = (j < 2) ? (2 + j) : (226 + j);
        xs[row][idx] = 0.f;
    }
    __syncthreads();

    // ---- Stream phase ----
    const int g4  = (tid % LRN_CG) * 4;     // shared base index of this col-group
    const int s   = tid / LRN_CG;           // row-group 0..3
    const int ti0 = s * LRN_R + 2;          // tile row of first output row
    const int sr0 = r0 + s * LRN_R;         // global first output row

    float4 bx;
    float4 hist[4];
    float4 xr[2];
    hist[0] = hsum_row(&xs[ti0 - 2][0], g4, &bx);
    hist[1] = hsum_row(&xs[ti0 - 1][0], g4, &bx);
    hist[2] = hsum_row(&xs[ti0    ][0], g4, &bx);  xr[0] = bx;
    hist[3] = hsum_row(&xs[ti0 + 1][0], g4, &bx);  xr[1] = bx;

    float4 vs;
    vs.x = hist[0].x + hist[1].x + hist[2].x + hist[3].x;
    vs.y = hist[0].y + hist[1].y + hist[2].y + hist[3].y;
    vs.z = hist[0].z + hist[1].z + hist[2].z + hist[3].z;
    vs.w = hist[0].w + hist[1].w + hist[2].w + hist[3].w;

    float* po = pout + (size_t)sr0 * LRN_W + g4;

    #pragma unroll
    for (int i = 0; i < LRN_R; ++i) {
        float4 hnew = hsum_row(&xs[ti0 + 2 + i][0], g4, &bx);

        float4 vf;                           // full vertical 5-tap ssq @ row sr0+i
        vf.x = vs.x + hnew.x;
        vf.y = vs.y + hnew.y;
        vf.z = vs.z + hnew.z;
        vf.w = vs.w + hnew.w;

        float4 xa = xr[i & 1];               // raw x at row sr0+i
        float4 val;
        val.x = xa.x * __powf(fmaf(1e-4f, vf.x, 2.0f), -0.75f);
        val.y = xa.y * __powf(fmaf(1e-4f, vf.y, 2.0f), -0.75f);
        val.z = xa.z * __powf(fmaf(1e-4f, vf.z, 2.0f), -0.75f);
        val.w = xa.w * __powf(fmaf(1e-4f, vf.w, 2.0f), -0.75f);

        *reinterpret_cast<float4*>(po) = val;
        po += LRN_W;

        float4 hold = hist[i & 3];           // h @ row sr0+i-2
        vs.x = vf.x - hold.x;
        vs.y = vf.y - hold.y;
        vs.z = vf.z - hold.z;
        vs.w = vf.w - hold.w;
        hist[i & 3] = hnew;
        xr[i & 1] = bx;
    }
}

extern "C" void kernel_launch(void* const* d_in, const int* in_sizes, int n_in,
                              void* d_out, int out_size) {
    const float* x = (const float*)d_in[0];
    float* out = (float*)d_out;
    (void)in_sizes; (void)n_in; (void)out_size;
    dim3 grid(16 * 96, LRN_H / LRN_TH);    // 1536 planes x 7 row-strips
    lrn_kernel<<<grid, 224>>>(x, out);
}